// round 14
// baseline (speedup 1.0000x reference)
#include <cuda_runtime.h>

// Problem constants (fixed by dataset: B=2, N=512, E=128, H=8, D=16)
#define B_    2
#define N_    512
#define E_    128
#define H_    8
#define D_    16
#define ROWS_ (B_ * N_)   // 1024

// Scratch (device globals: allocation-free rule)
__device__ float g_q[ROWS_ * E_];    // q * 0.25 (1/sqrt(D))
__device__ float g_v[ROWS_ * E_];

// ---------------- packed fp32x2 helpers (Blackwell FFMA2/FADD2) -------------
typedef unsigned long long u64;
#define ABS2_MASK 0x7fffffff7fffffffULL
#define FULLM 0xffffffffu

__device__ __forceinline__ u64 pack2(float lo, float hi) {
    u64 r; asm("mov.b64 %0, {%1, %2};" : "=l"(r) : "f"(lo), "f"(hi)); return r;
}
__device__ __forceinline__ float2 unpk2(u64 v) {
    float2 f; asm("mov.b64 {%0, %1}, %2;" : "=f"(f.x), "=f"(f.y) : "l"(v)); return f;
}
__device__ __forceinline__ u64 ffma2(u64 a, u64 b, u64 c) {
    u64 d; asm("fma.rn.f32x2 %0, %1, %2, %3;" : "=l"(d) : "l"(a), "l"(b), "l"(c)); return d;
}
__device__ __forceinline__ u64 fadd2(u64 a, u64 b) {
    u64 d; asm("add.rn.f32x2 %0, %1, %2;" : "=l"(d) : "l"(a), "l"(b)); return d;
}

// Butterfly transpose-reduce over 16 per-lane partials: returns, on lane L,
// the full 32-lane sum of pc[bitrev4(L & 15)].
__device__ __forceinline__ float butterfly16(float* pc, int lane) {
    #pragma unroll
    for (int r = 0; r < 4; r++) {
        const int half = 8 >> r;
        const bool hi = (lane >> r) & 1;
        #pragma unroll
        for (int j = 0; j < 8; j++) {
            if (j < half) {
                float send = hi ? pc[j] : pc[j + half];
                float keep = hi ? pc[j + half] : pc[j];
                float recv = __shfl_xor_sync(FULLM, send, 1 << r);
                pc[j] = keep + recv;
            }
        }
    }
    return pc[0] + __shfl_xor_sync(FULLM, pc[0], 16);
}
__device__ __forceinline__ int bitrev4(int l) {
    return ((l & 1) << 3) | (((l >> 1) & 1) << 2)
         | (((l >> 2) & 1) << 1) | ((l >> 3) & 1);
}

// ---------------------------------------------------------------------------
// qv GEMM: C[32r x 64c] = X[32 x 128] @ W[64 x 128]^T per CTA (R13, FFMA2).
// ---------------------------------------------------------------------------
#define QV_SMEM_BYTES (32 * 128 * 4 + 128 * 68 * 4)

__global__ __launch_bounds__(128) void qv_kernel(const float* __restrict__ x,
                                                 const float* __restrict__ w_qkv) {
    extern __shared__ float sm[];
    float (*x_s)[128] = (float(*)[128])sm;
    float (*w_s)[68]  = (float(*)[68])(sm + 32 * 128);

    const int tid  = threadIdx.x;
    const int row0 = blockIdx.y * 32;
    const int st   = blockIdx.x;                           // 0,1 -> q ; 2,3 -> v
    const int wbase = (st < 2) ? st * 64 : 128 + st * 64;  // 0,64,256,320
    const float* w_rows = w_qkv + wbase * 128;

    {
        const float4* x4 = (const float4*)(x + row0 * 128);
        float4* xs4 = (float4*)x_s;
        #pragma unroll
        for (int i = 0; i < 8; i++) xs4[tid + i * 128] = x4[tid + i * 128];
    }
    #pragma unroll
    for (int i = 0; i < 64; i++) {
        int idx = tid + i * 128;
        int j = idx & 127, c = idx >> 7;
        w_s[j][c] = w_rows[c * 128 + j];
    }
    __syncthreads();

    const int tx = tid & 15;
    const int ty = tid >> 4;
    u64 acc2[4][2];
    #pragma unroll
    for (int r = 0; r < 4; r++) { acc2[r][0] = 0ULL; acc2[r][1] = 0ULL; }

    #pragma unroll 4
    for (int jb = 0; jb < 32; jb++) {
        float4 xr[4], wv[4];
        #pragma unroll
        for (int r = 0; r < 4; r++) xr[r] = *(const float4*)&x_s[ty * 4 + r][jb * 4];
        #pragma unroll
        for (int k = 0; k < 4; k++) wv[k] = *(const float4*)&w_s[jb * 4 + k][tx * 4];
        #pragma unroll
        for (int k = 0; k < 4; k++) {
            const u64 w01 = pack2(wv[k].x, wv[k].y);
            const u64 w23 = pack2(wv[k].z, wv[k].w);
            #pragma unroll
            for (int r = 0; r < 4; r++) {
                float xs = (k == 0) ? xr[r].x : (k == 1) ? xr[r].y
                         : (k == 2) ? xr[r].z : xr[r].w;
                const u64 x2 = pack2(xs, xs);
                acc2[r][0] = ffma2(x2, w01, acc2[r][0]);
                acc2[r][1] = ffma2(x2, w23, acc2[r][1]);
            }
        }
    }

    const float scale = (st < 2) ? 0.25f : 1.0f;
    float* dst = (st < 2) ? g_q : g_v;
    const int cg = (st & 1) * 64 + tx * 4;
    #pragma unroll
    for (int r = 0; r < 4; r++) {
        float2 a01 = unpk2(acc2[r][0]);
        float2 a23 = unpk2(acc2[r][1]);
        float4 o = {a01.x * scale, a01.y * scale, a23.x * scale, a23.y * scale};
        *(float4*)&dst[(row0 + ty * 4 + r) * 128 + cg] = o;
    }
}

// ---------------------------------------------------------------------------
// Attention + projection with active-dimension folding (R13) + BATCHED
// phase-2 reduction: all active-d partial sums collected into pcA[16]
// (static indices) and reduced with ONE butterfly16 instead of LV serial
// 5-shuffle chains. rank->d scatter via tiny smem map.
// ---------------------------------------------------------------------------
__global__ __launch_bounds__(256, 3) void attn_proj_kernel(const float* __restrict__ e,
                                                           const float* __restrict__ w_ekv,
                                                           const float* __restrict__ b_ekv,
                                                           const float* __restrict__ w_prj,
                                                           const float* __restrict__ b_prj,
                                                           float* __restrict__ out) {
    __shared__ float e_s[N_];
    __shared__ float q_s[128], v_s[128];
    __shared__ float wk_s[128], bk_s[128], wv_s[128], bv_s[128];
    __shared__ float hat_s[128];
    __shared__ float corr_s[128];
    __shared__ int   rank2d_s[H_][16];

    const int row  = blockIdx.x;     // b*N + n
    const int tid  = threadIdx.x;
    const int lane = tid & 31;
    const int h    = tid >> 5;       // warp == head

    if (tid < 128)
        ((float4*)e_s)[tid] = ((const float4*)(e + row * N_))[tid];
    if (tid < 128) {
        q_s[tid]  = g_q[row * 128 + tid];
        v_s[tid]  = g_v[row * 128 + tid];
        wk_s[tid] = w_ekv[tid];
        bk_s[tid] = b_ekv[tid];
    } else {
        int t = tid - 128;
        wv_s[t] = w_ekv[128 + t];
        bv_s[t] = b_ekv[128 + t];
    }
    __syncthreads();

    // ---- all 16 m values of this lane, packed as 8 (m, m+256) pairs ----
    u64 em2[8];
    #pragma unroll
    for (int i = 0; i < 8; i++)
        em2[i] = pack2(e_s[i * 32 + lane], e_s[i * 32 + 256 + lane]);

    // ======== K-side classification (lane<16 owns d=lane) ========
    float wK = 0.f, bK = 0.f, qd = 0.f;
    if (lane < 16) {
        wK = wk_s[h * 16 + lane];
        bK = bk_s[h * 16 + lane];
        qd = q_s[h * 16 + lane];
    }
    float rK = __fdividef(bK, wK);          // lane>=16: nan -> inactive
    bool actK = (rK > -1.f) && (rK < 0.f);  // root -r in (0,1)
    float gK = 0.495f * qd * fabsf(wK);
    float c1 , c0;
    if (actK) { c1 = 0.505f * qd * wK; c0 = 0.505f * qd * bK; }
    else {
        bool pos = (fmaf(0.5f, wK, bK) > 0.f);   // constant-sign branch
        c1 = qd * (pos ? wK : 0.01f * wK);
        c0 = qd * (pos ? bK : 0.01f * bK);
    }
    #pragma unroll
    for (int k = 16; k >= 1; k >>= 1) {
        c1 += __shfl_xor_sync(FULLM, c1, k);
        c0 += __shfl_xor_sync(FULLM, c0, k);
    }
    const unsigned mK = __ballot_sync(FULLM, actK);

    // ======== phase 1: d-outer over active K dims ========
    u64 s2[8];
    #pragma unroll
    for (int i = 0; i < 8; i++) s2[i] = 0ULL;
    for (unsigned mm = mK; mm; mm &= (mm - 1)) {
        int d = __ffs(mm) - 1;
        float r = __shfl_sync(FULLM, rK, d);
        float g = __shfl_sync(FULLM, gK, d);
        u64 r2 = pack2(r, r);
        u64 g2 = pack2(g, g);
        #pragma unroll
        for (int i = 0; i < 8; i++)
            s2[i] = ffma2(g2, fadd2(em2[i], r2) & ABS2_MASK, s2[i]);
    }
    float s[16];
    #pragma unroll
    for (int i = 0; i < 8; i++) {
        float2 f  = unpk2(s2[i]);
        float2 ee = unpk2(em2[i]);
        s[i]     = fmaf(c1, ee.x, c0) + f.x;
        s[i + 8] = fmaf(c1, ee.y, c0) + f.y;
    }

    // ======== softmax over m (+ S1 = sum p*em) ========
    float mx = s[0];
    #pragma unroll
    for (int i = 1; i < 16; i++) mx = fmaxf(mx, s[i]);
    #pragma unroll
    for (int k = 16; k >= 1; k >>= 1) mx = fmaxf(mx, __shfl_xor_sync(FULLM, mx, k));
    float Z = 0.f, S1 = 0.f;
    #pragma unroll
    for (int i = 0; i < 8; i++) {
        float2 ee = unpk2(em2[i]);
        float pa = __expf(s[i] - mx);
        float pb = __expf(s[i + 8] - mx);
        Z += pa + pb;
        S1 = fmaf(pa, ee.x, fmaf(pb, ee.y, S1));
        s[i] = pa; s[i + 8] = pb;
    }
    #pragma unroll
    for (int k = 16; k >= 1; k >>= 1) {
        Z  += __shfl_xor_sync(FULLM, Z, k);
        S1 += __shfl_xor_sync(FULLM, S1, k);
    }
    const float invZ = 1.f / Z;

    u64 p2[8];
    #pragma unroll
    for (int i = 0; i < 8; i++) p2[i] = pack2(s[i], s[i + 8]);

    // ======== V-side classification ========
    float wV = 0.f, bV = 0.f, vD = 0.f;
    if (lane < 16) {
        wV = wv_s[h * 16 + lane];
        bV = bv_s[h * 16 + lane];
        vD = v_s[h * 16 + lane];
    }
    float rV = __fdividef(bV, wV);
    bool actV = (rV > -1.f) && (rV < 0.f);
    const unsigned mV = __ballot_sync(FULLM, actV);
    const int LV = __popc(mV);

    // ======== phase 2: batched per-d partials, ONE butterfly reduce ========
    float pcA[16];
    {
        unsigned mm = mV;
        #pragma unroll
        for (int rk = 0; rk < 16; rk++) {
            float val = 0.f;
            if (mm) {                              // warp-uniform guard
                int d = __ffs(mm) - 1;
                mm &= (mm - 1);
                if (lane == 0) rank2d_s[h][rk] = d;
                float r = __shfl_sync(FULLM, rV, d);
                u64 r2 = pack2(r, r);
                u64 a2 = 0ULL;
                #pragma unroll
                for (int i = 0; i < 8; i++)
                    a2 = ffma2(p2[i], fadd2(em2[i], r2) & ABS2_MASK, a2);
                float2 f = unpk2(a2);
                val = f.x + f.y;
            }
            pcA[rk] = val;
        }
    }
    float totA = butterfly16(pcA, lane);     // lane L: total for rank bitrev4(L)
    __syncwarp();
    {
        int rb = bitrev4(lane);
        if (rb < LV) corr_s[h * 16 + rank2d_s[h][rb]] = totA;
    }
    __syncwarp();

    // ======== epilogue: hat ========
    if (lane < 16) {
        float hat;
        if (actV) {
            hat = vD + (0.505f * fmaf(wV, S1, bV * Z)
                        + 0.495f * fabsf(wV) * corr_s[h * 16 + lane]) * invZ;
        } else {
            bool pos = (fmaf(0.5f, wV, bV) > 0.f);
            float sl = pos ? wV : 0.01f * wV;
            float ic = pos ? bV : 0.01f * bV;
            hat = vD + fmaf(sl, S1, ic * Z) * invZ;
        }
        hat_s[h * 16 + lane] = hat;
    }
    __syncthreads();

    // ======== projection: warp h -> cols [h*16, h*16+16) ========
    {
        float4 h4 = ((const float4*)hat_s)[lane];
        float pc[16];
        #pragma unroll
        for (int i = 0; i < 16; i++) {
            const int c = h * 16 + i;
            float4 wv = *(const float4*)&w_prj[c * 128 + lane * 4];
            pc[i] = fmaf(h4.x, wv.x, fmaf(h4.y, wv.y, fmaf(h4.z, wv.z, h4.w * wv.w)));
        }
        float cval = butterfly16(pc, lane);
        if (lane < 16) {
            const int c = h * 16 + bitrev4(lane);
            out[row * 128 + c] = cval + b_prj[c];
        }
    }
}

// ---------------------------------------------------------------------------
extern "C" void kernel_launch(void* const* d_in, const int* in_sizes, int n_in,
                              void* d_out, int out_size) {
    const float* x     = (const float*)d_in[0];
    const float* e     = (const float*)d_in[1];
    const float* w_qkv = (const float*)d_in[2];
    const float* w_ekv = (const float*)d_in[3];
    const float* b_ekv = (const float*)d_in[4];
    const float* w_prj = (const float*)d_in[5];
    const float* b_prj = (const float*)d_in[6];
    float* out = (float*)d_out;

    cudaFuncSetAttribute((const void*)qv_kernel,
                         cudaFuncAttributeMaxDynamicSharedMemorySize, QV_SMEM_BYTES);

    qv_kernel       <<<dim3(4, 32), 128, QV_SMEM_BYTES>>>(x, w_qkv);
    attn_proj_kernel<<<ROWS_,       256>>>(e, w_ekv, b_ekv, w_prj, b_prj, out);
}

// round 15
// speedup vs baseline: 1.0111x; 1.0111x over previous
#include <cuda_runtime.h>

// Problem constants (fixed by dataset: B=2, N=512, E=128, H=8, D=16)
#define B_    2
#define N_    512
#define E_    128
#define H_    8
#define D_    16
#define ROWS_ (B_ * N_)   // 1024

// Scratch (device globals: allocation-free rule)
__device__ float g_q[ROWS_ * E_];    // q * 0.25 (1/sqrt(D))
__device__ float g_v[ROWS_ * E_];

// ---------------- packed fp32x2 helpers (Blackwell FFMA2/FADD2) -------------
typedef unsigned long long u64;
#define ABS2_MASK 0x7fffffff7fffffffULL
#define FULLM 0xffffffffu

__device__ __forceinline__ u64 pack2(float lo, float hi) {
    u64 r; asm("mov.b64 %0, {%1, %2};" : "=l"(r) : "f"(lo), "f"(hi)); return r;
}
__device__ __forceinline__ float2 unpk2(u64 v) {
    float2 f; asm("mov.b64 {%0, %1}, %2;" : "=f"(f.x), "=f"(f.y) : "l"(v)); return f;
}
__device__ __forceinline__ u64 ffma2(u64 a, u64 b, u64 c) {
    u64 d; asm("fma.rn.f32x2 %0, %1, %2, %3;" : "=l"(d) : "l"(a), "l"(b), "l"(c)); return d;
}
__device__ __forceinline__ u64 fadd2(u64 a, u64 b) {
    u64 d; asm("add.rn.f32x2 %0, %1, %2;" : "=l"(d) : "l"(a), "l"(b)); return d;
}

// Butterfly transpose-reduce over 16 per-lane partials: returns, on lane L,
// the full 32-lane sum of pc[bitrev4(L & 15)].
__device__ __forceinline__ float butterfly16(float* pc, int lane) {
    #pragma unroll
    for (int r = 0; r < 4; r++) {
        const int half = 8 >> r;
        const bool hi = (lane >> r) & 1;
        #pragma unroll
        for (int j = 0; j < 8; j++) {
            if (j < half) {
                float send = hi ? pc[j] : pc[j + half];
                float keep = hi ? pc[j + half] : pc[j];
                float recv = __shfl_xor_sync(FULLM, send, 1 << r);
                pc[j] = keep + recv;
            }
        }
    }
    return pc[0] + __shfl_xor_sync(FULLM, pc[0], 16);
}
__device__ __forceinline__ int bitrev4(int l) {
    return ((l & 1) << 3) | (((l >> 1) & 1) << 2)
         | (((l >> 2) & 1) << 1) | ((l >> 3) & 1);
}

// ---------------------------------------------------------------------------
// qv GEMM: C[32r x 64c] = X[32 x 128] @ W[64 x 128]^T per CTA (R13, FFMA2)
// + PDL completion trigger.
// ---------------------------------------------------------------------------
#define QV_SMEM_BYTES (32 * 128 * 4 + 128 * 68 * 4)

__global__ __launch_bounds__(128) void qv_kernel(const float* __restrict__ x,
                                                 const float* __restrict__ w_qkv) {
    extern __shared__ float sm[];
    float (*x_s)[128] = (float(*)[128])sm;
    float (*w_s)[68]  = (float(*)[68])(sm + 32 * 128);

    const int tid  = threadIdx.x;
    const int row0 = blockIdx.y * 32;
    const int st   = blockIdx.x;                           // 0,1 -> q ; 2,3 -> v
    const int wbase = (st < 2) ? st * 64 : 128 + st * 64;  // 0,64,256,320
    const float* w_rows = w_qkv + wbase * 128;

    {
        const float4* x4 = (const float4*)(x + row0 * 128);
        float4* xs4 = (float4*)x_s;
        #pragma unroll
        for (int i = 0; i < 8; i++) xs4[tid + i * 128] = x4[tid + i * 128];
    }
    #pragma unroll
    for (int i = 0; i < 64; i++) {
        int idx = tid + i * 128;
        int j = idx & 127, c = idx >> 7;
        w_s[j][c] = w_rows[c * 128 + j];
    }
    __syncthreads();

    const int tx = tid & 15;
    const int ty = tid >> 4;
    u64 acc2[4][2];
    #pragma unroll
    for (int r = 0; r < 4; r++) { acc2[r][0] = 0ULL; acc2[r][1] = 0ULL; }

    #pragma unroll 4
    for (int jb = 0; jb < 32; jb++) {
        float4 xr[4], wv[4];
        #pragma unroll
        for (int r = 0; r < 4; r++) xr[r] = *(const float4*)&x_s[ty * 4 + r][jb * 4];
        #pragma unroll
        for (int k = 0; k < 4; k++) wv[k] = *(const float4*)&w_s[jb * 4 + k][tx * 4];
        #pragma unroll
        for (int k = 0; k < 4; k++) {
            const u64 w01 = pack2(wv[k].x, wv[k].y);
            const u64 w23 = pack2(wv[k].z, wv[k].w);
            #pragma unroll
            for (int r = 0; r < 4; r++) {
                float xs = (k == 0) ? xr[r].x : (k == 1) ? xr[r].y
                         : (k == 2) ? xr[r].z : xr[r].w;
                const u64 x2 = pack2(xs, xs);
                acc2[r][0] = ffma2(x2, w01, acc2[r][0]);
                acc2[r][1] = ffma2(x2, w23, acc2[r][1]);
            }
        }
    }

    const float scale = (st < 2) ? 0.25f : 1.0f;
    float* dst = (st < 2) ? g_q : g_v;
    const int cg = (st & 1) * 64 + tx * 4;
    #pragma unroll
    for (int r = 0; r < 4; r++) {
        float2 a01 = unpk2(acc2[r][0]);
        float2 a23 = unpk2(acc2[r][1]);
        float4 o = {a01.x * scale, a01.y * scale, a23.x * scale, a23.y * scale};
        *(float4*)&dst[(row0 + ty * 4 + r) * 128 + cg] = o;
    }

#if __CUDA_ARCH__ >= 900
    cudaTriggerProgrammaticLaunchCompletion();
#endif
}

// ---------------------------------------------------------------------------
// Attention + projection (active-dimension folding, R14 engine) with a DEEP
// PDL pre-wait section: e staging, em2 packing, and the q-independent parts
// of K/V classification all run before cudaGridDependencySynchronize().
// Phase 1 processes two active d's per loop iteration (ILP + fewer branches).
// ---------------------------------------------------------------------------
__global__ __launch_bounds__(256, 3) void attn_proj_kernel(const float* __restrict__ e,
                                                           const float* __restrict__ w_ekv,
                                                           const float* __restrict__ b_ekv,
                                                           const float* __restrict__ w_prj,
                                                           const float* __restrict__ b_prj,
                                                           float* __restrict__ out) {
    __shared__ float e_s[N_];
    __shared__ float q_s[128], v_s[128];
    __shared__ float wk_s[128], bk_s[128], wv_s[128], bv_s[128];
    __shared__ float hat_s[128];
    __shared__ float corr_s[128];
    __shared__ int   rank2d_s[H_][16];

    const int row  = blockIdx.x;     // b*N + n
    const int tid  = threadIdx.x;
    const int lane = tid & 31;
    const int h    = tid >> 5;       // warp == head

    // ======== PRE-WAIT: everything q/v-independent ========
    ((float2*)e_s)[tid] = ((const float2*)(e + row * N_))[tid];
    if (tid < 128) {
        wk_s[tid] = w_ekv[tid];
        bk_s[tid] = b_ekv[tid];
    } else {
        int t = tid - 128;
        wv_s[t] = w_ekv[128 + t];
        bv_s[t] = b_ekv[128 + t];
    }
    __syncthreads();

    // all 16 m values of this lane, packed as 8 (m, m+256) pairs
    u64 em2[8];
    #pragma unroll
    for (int i = 0; i < 8; i++)
        em2[i] = pack2(e_s[i * 32 + lane], e_s[i * 32 + 256 + lane]);

    // K-side classification, q-independent part (lane<16 owns d=lane)
    float wK = 0.f, bK = 0.f;
    if (lane < 16) {
        wK = wk_s[h * 16 + lane];
        bK = bk_s[h * 16 + lane];
    }
    float rK = __fdividef(bK, wK);          // lane>=16: nan -> inactive
    bool actK = (rK > -1.f) && (rK < 0.f);  // root -r in (0,1)
    const unsigned mK = __ballot_sync(FULLM, actK);

    // V-side classification (fully q-independent)
    float wV = 0.f, bV = 0.f;
    if (lane < 16) {
        wV = wv_s[h * 16 + lane];
        bV = bv_s[h * 16 + lane];
    }
    float rV = __fdividef(bV, wV);
    bool actV = (rV > -1.f) && (rV < 0.f);
    const unsigned mV = __ballot_sync(FULLM, actV);
    const int LV = __popc(mV);

    // ======== WAIT for qv_kernel, then load q/v ========
#if __CUDA_ARCH__ >= 900
    cudaGridDependencySynchronize();
#endif
    if (tid < 128) {
        q_s[tid] = g_q[row * 128 + tid];
        v_s[tid] = g_v[row * 128 + tid];
    }
    __syncthreads();

    // q-dependent per-head constants
    float qd = 0.f, vD = 0.f;
    if (lane < 16) {
        qd = q_s[h * 16 + lane];
        vD = v_s[h * 16 + lane];
    }
    float gK = 0.495f * qd * fabsf(wK);
    float c1, c0;
    if (actK) { c1 = 0.505f * qd * wK; c0 = 0.505f * qd * bK; }
    else {
        bool pos = (fmaf(0.5f, wK, bK) > 0.f);   // constant-sign branch
        c1 = qd * (pos ? wK : 0.01f * wK);
        c0 = qd * (pos ? bK : 0.01f * bK);
    }
    #pragma unroll
    for (int k = 16; k >= 1; k >>= 1) {
        c1 += __shfl_xor_sync(FULLM, c1, k);
        c0 += __shfl_xor_sync(FULLM, c0, k);
    }

    // ======== phase 1: d-outer over active K dims, 2 per iteration ========
    u64 s2[8];
    #pragma unroll
    for (int i = 0; i < 8; i++) s2[i] = 0ULL;
    {
        unsigned mm = mK;
        while (mm) {
            int d0 = __ffs(mm) - 1; mm &= (mm - 1);
            float r0 = __shfl_sync(FULLM, rK, d0);
            float g0 = __shfl_sync(FULLM, gK, d0);
            u64 r20 = pack2(r0, r0), g20 = pack2(g0, g0);
            if (mm) {
                int d1 = __ffs(mm) - 1; mm &= (mm - 1);
                float r1 = __shfl_sync(FULLM, rK, d1);
                float g1 = __shfl_sync(FULLM, gK, d1);
                u64 r21 = pack2(r1, r1), g21 = pack2(g1, g1);
                #pragma unroll
                for (int i = 0; i < 8; i++) {
                    u64 u0 = fadd2(em2[i], r20) & ABS2_MASK;
                    u64 u1 = fadd2(em2[i], r21) & ABS2_MASK;
                    s2[i] = ffma2(g20, u0, s2[i]);
                    s2[i] = ffma2(g21, u1, s2[i]);
                }
            } else {
                #pragma unroll
                for (int i = 0; i < 8; i++)
                    s2[i] = ffma2(g20, fadd2(em2[i], r20) & ABS2_MASK, s2[i]);
            }
        }
    }
    float s[16];
    #pragma unroll
    for (int i = 0; i < 8; i++) {
        float2 f  = unpk2(s2[i]);
        float2 ee = unpk2(em2[i]);
        s[i]     = fmaf(c1, ee.x, c0) + f.x;
        s[i + 8] = fmaf(c1, ee.y, c0) + f.y;
    }

    // ======== softmax over m (+ S1 = sum p*em) ========
    float mx = s[0];
    #pragma unroll
    for (int i = 1; i < 16; i++) mx = fmaxf(mx, s[i]);
    #pragma unroll
    for (int k = 16; k >= 1; k >>= 1) mx = fmaxf(mx, __shfl_xor_sync(FULLM, mx, k));
    float Z = 0.f, S1 = 0.f;
    #pragma unroll
    for (int i = 0; i < 8; i++) {
        float2 ee = unpk2(em2[i]);
        float pa = __expf(s[i] - mx);
        float pb = __expf(s[i + 8] - mx);
        Z += pa + pb;
        S1 = fmaf(pa, ee.x, fmaf(pb, ee.y, S1));
        s[i] = pa; s[i + 8] = pb;
    }
    #pragma unroll
    for (int k = 16; k >= 1; k >>= 1) {
        Z  += __shfl_xor_sync(FULLM, Z, k);
        S1 += __shfl_xor_sync(FULLM, S1, k);
    }
    const float invZ = 1.f / Z;

    u64 p2[8];
    #pragma unroll
    for (int i = 0; i < 8; i++) p2[i] = pack2(s[i], s[i + 8]);

    // ======== phase 2: batched per-d partials, ONE butterfly reduce ========
    float pcA[16];
    {
        unsigned mm = mV;
        #pragma unroll
        for (int rk = 0; rk < 16; rk++) {
            float val = 0.f;
            if (mm) {                              // warp-uniform guard
                int d = __ffs(mm) - 1;
                mm &= (mm - 1);
                if (lane == 0) rank2d_s[h][rk] = d;
                float r = __shfl_sync(FULLM, rV, d);
                u64 r2 = pack2(r, r);
                u64 a2 = 0ULL;
                #pragma unroll
                for (int i = 0; i < 8; i++)
                    a2 = ffma2(p2[i], fadd2(em2[i], r2) & ABS2_MASK, a2);
                float2 f = unpk2(a2);
                val = f.x + f.y;
            }
            pcA[rk] = val;
        }
    }
    float totA = butterfly16(pcA, lane);     // lane L: total for rank bitrev4(L)
    __syncwarp();
    {
        int rb = bitrev4(lane);
        if (rb < LV) corr_s[h * 16 + rank2d_s[h][rb]] = totA;
    }
    __syncwarp();

    // ======== epilogue: hat ========
    if (lane < 16) {
        float hat;
        if (actV) {
            hat = vD + (0.505f * fmaf(wV, S1, bV * Z)
                        + 0.495f * fabsf(wV) * corr_s[h * 16 + lane]) * invZ;
        } else {
            bool pos = (fmaf(0.5f, wV, bV) > 0.f);
            float sl = pos ? wV : 0.01f * wV;
            float ic = pos ? bV : 0.01f * bV;
            hat = vD + fmaf(sl, S1, ic * Z) * invZ;
        }
        hat_s[h * 16 + lane] = hat;
    }
    __syncthreads();

    // ======== projection: warp h -> cols [h*16, h*16+16) ========
    {
        float4 h4 = ((const float4*)hat_s)[lane];
        float pc[16];
        #pragma unroll
        for (int i = 0; i < 16; i++) {
            const int c = h * 16 + i;
            float4 wv = *(const float4*)&w_prj[c * 128 + lane * 4];
            pc[i] = fmaf(h4.x, wv.x, fmaf(h4.y, wv.y, fmaf(h4.z, wv.z, h4.w * wv.w)));
        }
        float cval = butterfly16(pc, lane);
        if (lane < 16) {
            const int c = h * 16 + bitrev4(lane);
            out[row * 128 + c] = cval + b_prj[c];
        }
    }
}

// ---------------------------------------------------------------------------
extern "C" void kernel_launch(void* const* d_in, const int* in_sizes, int n_in,
                              void* d_out, int out_size) {
    const float* x     = (const float*)d_in[0];
    const float* e     = (const float*)d_in[1];
    const float* w_qkv = (const float*)d_in[2];
    const float* w_ekv = (const float*)d_in[3];
    const float* b_ekv = (const float*)d_in[4];
    const float* w_prj = (const float*)d_in[5];
    const float* b_prj = (const float*)d_in[6];
    float* out = (float*)d_out;

    cudaFuncSetAttribute((const void*)qv_kernel,
                         cudaFuncAttributeMaxDynamicSharedMemorySize, QV_SMEM_BYTES);

    qv_kernel<<<dim3(4, 32), 128, QV_SMEM_BYTES>>>(x, w_qkv);

    // PDL launch of the dependent kernel; fall back to a plain launch if the
    // attribute is rejected on this driver/toolkit.
    cudaLaunchConfig_t cfg = {};
    cfg.gridDim  = dim3(ROWS_);
    cfg.blockDim = dim3(256);
    cfg.dynamicSmemBytes = 0;
    cudaLaunchAttribute attrs[1];
    attrs[0].id = cudaLaunchAttributeProgrammaticStreamSerialization;
    attrs[0].val.programmaticStreamSerializationAllowed = 1;
    cfg.attrs = attrs;
    cfg.numAttrs = 1;
    cudaError_t err = cudaLaunchKernelEx(&cfg, attn_proj_kernel,
                                         e, w_ekv, b_ekv, w_prj, b_prj, out);
    if (err != cudaSuccess) {
        attn_proj_kernel<<<ROWS_, 256>>>(e, w_ekv, b_ekv, w_prj, b_prj, out);
    }
}